// round 5
// baseline (speedup 1.0000x reference)
#include <cuda_runtime.h>
#include <cuda_fp16.h>
#include <cstdint>

#define B_   4
#define M_   65536
#define N_   16384
#define D_   128

#define OFF_IDX 0                 // 64 ints (fuse)
#define OFF_SA  1024              // w tile  [64k][136 halfs] = 17408 B
#define OFF_SB  (1024 + 17408)    // x tile  [64k][136 halfs] = 17408 B
#define SMEM_TOTAL (1024 + 2 * 17408)   // 35840
#define OFF_STG 1024              // stage [128d][67 words] fp32 = 34304 B (aliases SA+SB)
#define SPITCH  67
#define PITCHB  272               // 136 halfs * 2 bytes

__device__ float g_Z[(size_t)B_ * N_ * D_];   // 32 MB scratch [b][n][d]
__device__ int g_idx_is64;

// ---------------- helpers ----------------
static __device__ __forceinline__ uint32_t s2u(const void* p) {
    uint32_t a;
    asm("{ .reg .u64 t; cvta.to.shared.u64 t, %1; cvt.u32.u64 %0, t; }" : "=r"(a) : "l"(p));
    return a;
}
// pack two fp32 -> f16x2 {lo, hi}
static __device__ __forceinline__ uint32_t pk(float lo, float hi) {
    uint32_t r;
    asm("cvt.rn.f16x2.f32 %0, %1, %2;" : "=r"(r) : "f"(hi), "f"(lo));
    return r;
}
static __device__ __forceinline__ void mma_f16(float* c, const uint32_t* a,
                                               uint32_t b0, uint32_t b1) {
    asm volatile(
        "mma.sync.aligned.m16n8k16.row.col.f32.f16.f16.f32 "
        "{%0,%1,%2,%3}, {%4,%5,%6,%7}, {%8,%9}, {%0,%1,%2,%3};"
        : "+f"(c[0]), "+f"(c[1]), "+f"(c[2]), "+f"(c[3])
        : "r"(a[0]), "r"(a[1]), "r"(a[2]), "r"(a[3]), "r"(b0), "r"(b1));
}
#define LDSM4T(r0, r1, r2, r3, a) \
    asm volatile("ldmatrix.sync.aligned.m8n8.x4.trans.shared.b16 {%0,%1,%2,%3}, [%4];" \
                 : "=r"(r0), "=r"(r1), "=r"(r2), "=r"(r3) : "r"(a))
#define LDSM2T(r0, r1, a) \
    asm volatile("ldmatrix.sync.aligned.m8n8.x2.trans.shared.b16 {%0,%1}, [%2];" \
                 : "=r"(r0), "=r"(r1) : "r"(a))

// convert 64 rows x (C4*4) fp32 cols -> f16 smem tile [k][col], pitch 272B
template <int C4>
static __device__ __forceinline__ void conv_tile(char* smc, int offs,
                                                 const float* __restrict__ src,
                                                 size_t stride, int t) {
#pragma unroll
    for (int idx = t, it = 0; it < 64 * C4 / 128; it++, idx += 128) {
        int k = idx / C4, c = idx % C4;
        float4 v = *(const float4*)(src + (size_t)k * stride + c * 4);
        uint2 u = make_uint2(pk(v.x, v.y), pk(v.z, v.w));
        *(uint2*)(smc + offs + k * PITCHB + c * 8) = u;
    }
}

// mainloop over one K=64 chunk: warp tile 64d x 32tok, 64 MMAs
static __device__ __forceinline__ void compute_chunk(uint32_t sb, int wm, int wn, int lane,
                                                     float acc[4][4][4]) {
    const int aRow = (lane & 7) | ((lane & 16) >> 1);   // k offset 0..15
    const int aCol = (lane & 8);                        // +8 d for mats 1,3
    const int bRow = lane & 15;
#pragma unroll
    for (int ks = 0; ks < 4; ks++) {
        uint32_t A[4][4];
#pragma unroll
        for (int mt = 0; mt < 4; mt++)
            LDSM4T(A[mt][0], A[mt][1], A[mt][2], A[mt][3],
                   sb + OFF_SA + (ks * 16 + aRow) * PITCHB +
                       (wm * 64 + mt * 16 + aCol) * 2);
        uint32_t Bf[4][2];
#pragma unroll
        for (int nt = 0; nt < 4; nt++)
            LDSM2T(Bf[nt][0], Bf[nt][1],
                   sb + OFF_SB + (ks * 16 + bRow) * PITCHB + (wn * 32 + nt * 8) * 2);
#pragma unroll
        for (int mt = 0; mt < 4; mt++)
#pragma unroll
            for (int nt = 0; nt < 4; nt++)
                mma_f16(acc[mt][nt], A[mt], Bf[nt][0], Bf[nt][1]);
    }
}

static __device__ __forceinline__ void stage_acc(char* smc, int wm, int wn, int lane,
                                                 float acc[4][4][4]) {
    float* stg = (float*)(smc + OFF_STG);
    const int r = lane >> 2, q2 = (lane & 3) * 2;
#pragma unroll
    for (int mt = 0; mt < 4; mt++)
#pragma unroll
        for (int nt = 0; nt < 4; nt++) {
            int d = wm * 64 + mt * 16 + r;
            int tk = wn * 32 + nt * 8 + q2;
            stg[d * SPITCH + tk]           = acc[mt][nt][0];
            stg[d * SPITCH + tk + 1]       = acc[mt][nt][1];
            stg[(d + 8) * SPITCH + tk]     = acc[mt][nt][2];
            stg[(d + 8) * SPITCH + tk + 1] = acc[mt][nt][3];
        }
}

// ---------------- GEMM 1: Z[b][n][d] = cur_x[b,:,n] @ w[64: ,:] ----------------
__global__ void __launch_bounds__(128, 4) zgemm(const float* __restrict__ cur,
                                                const float* __restrict__ w,
                                                const void* __restrict__ up_idx) {
    extern __shared__ char smc[];
    uint32_t sb = s2u(smc);
    const int t = threadIdx.x, lane = t & 31, wid = t >> 5;
    const int wm = wid & 1, wn = wid >> 1;
    const int bb = blockIdx.y, tok0 = blockIdx.x * 64;

    if (blockIdx.x == 0 && blockIdx.y == 0 && t == 0) {   // idx dtype probe for fuse
        const long long* p = (const long long*)up_idx;
        int ok = 1;
        for (int i = 0; i < 64; i++) {
            long long v = p[i];
            if (v < 0 || v >= N_) { ok = 0; break; }
        }
        g_idx_is64 = ok;
    }

    float acc[4][4][4];
#pragma unroll
    for (int a = 0; a < 4; a++)
#pragma unroll
        for (int b = 0; b < 4; b++)
#pragma unroll
            for (int c = 0; c < 4; c++) acc[a][b][c] = 0.0f;

    const float* xb = cur + (size_t)bb * 128 * N_ + tok0;
#pragma unroll
    for (int c = 0; c < 2; c++) {
        conv_tile<32>(smc, OFF_SA, w + (size_t)(64 + c * 64) * D_, D_, t);
        conv_tile<16>(smc, OFF_SB, xb + (size_t)c * 64 * N_, N_, t);
        __syncthreads();
        compute_chunk(sb, wm, wn, lane, acc);
        __syncthreads();
    }
    stage_acc(smc, wm, wn, lane, acc);
    __syncthreads();

    const float* stg = (const float*)(smc + OFF_STG);
    float* zb = g_Z + ((size_t)bb * N_ + tok0) * D_;
#pragma unroll
    for (int p = 0; p < 2; p++) {
        int tok = p * 32 + lane;
#pragma unroll
        for (int i = 0; i < 8; i++) {
            int d0 = wid * 32 + i * 4;
            float4 v;
            v.x = stg[(d0 + 0) * SPITCH + tok];
            v.y = stg[(d0 + 1) * SPITCH + tok];
            v.z = stg[(d0 + 2) * SPITCH + tok];
            v.w = stg[(d0 + 3) * SPITCH + tok];
            *(float4*)(zb + (size_t)tok * D_ + d0) = v;
        }
    }
}

// ---------------- GEMM 2 + gather + BN + relu ----------------
__global__ void __launch_bounds__(128, 4) fuse(const float* __restrict__ pre,
                                               const float* __restrict__ w,
                                               const void* __restrict__ up_idx,
                                               const float* __restrict__ bias,
                                               const float* __restrict__ gamma,
                                               const float* __restrict__ beta,
                                               const float* __restrict__ rmean,
                                               const float* __restrict__ rvar,
                                               float* __restrict__ out) {
    extern __shared__ char smc[];
    uint32_t sb = s2u(smc);
    const int t = threadIdx.x, lane = t & 31, wid = t >> 5;
    const int wm = wid & 1, wn = wid >> 1;
    const int bb = blockIdx.y, tok0 = blockIdx.x * 64;

    int* sIdx = (int*)(smc + OFF_IDX);
    if (t < 64) {
        size_t ip = (size_t)bb * M_ + tok0 + t;
        sIdx[t] = g_idx_is64 ? (int)((const long long*)up_idx)[ip]
                             : ((const int*)up_idx)[ip];
    }

    float acc[4][4][4];
#pragma unroll
    for (int a = 0; a < 4; a++)
#pragma unroll
        for (int b = 0; b < 4; b++)
#pragma unroll
            for (int c = 0; c < 4; c++) acc[a][b][c] = 0.0f;

    conv_tile<32>(smc, OFF_SA, w, D_, t);
    conv_tile<16>(smc, OFF_SB, pre + (size_t)bb * 64 * M_ + tok0, M_, t);
    __syncthreads();
    compute_chunk(sb, wm, wn, lane, acc);
    __syncthreads();
    stage_acc(smc, wm, wn, lane, acc);

    // BN fold for this warp's 32-d span (computed while stage settles)
    float4 s4[8], t4[8];
#pragma unroll
    for (int i = 0; i < 8; i++) {
        int d0 = wid * 32 + i * 4;
        float4 rv = *(const float4*)(rvar + d0);
        float4 gm = *(const float4*)(gamma + d0);
        float4 bi = *(const float4*)(bias + d0);
        float4 rm = *(const float4*)(rmean + d0);
        float4 be = *(const float4*)(beta + d0);
        s4[i].x = rsqrtf(rv.x + 1e-5f) * gm.x;
        s4[i].y = rsqrtf(rv.y + 1e-5f) * gm.y;
        s4[i].z = rsqrtf(rv.z + 1e-5f) * gm.z;
        s4[i].w = rsqrtf(rv.w + 1e-5f) * gm.w;
        t4[i].x = (bi.x - rm.x) * s4[i].x + be.x;
        t4[i].y = (bi.y - rm.y) * s4[i].y + be.y;
        t4[i].z = (bi.z - rm.z) * s4[i].z + be.z;
        t4[i].w = (bi.w - rm.w) * s4[i].w + be.w;
    }
    __syncthreads();

    const float* stg = (const float*)(smc + OFF_STG);
    const float* zB = g_Z + (size_t)bb * N_ * D_;
    float* ob = out + ((size_t)bb * M_ + tok0) * D_;
#pragma unroll
    for (int p = 0; p < 2; p++) {
        int tok = p * 32 + lane;
        const float4* zr = (const float4*)(zB + (size_t)sIdx[tok] * D_ + wid * 32);
        float4 z[8];
#pragma unroll
        for (int i = 0; i < 8; i++) z[i] = zr[i];     // deep MLP gather (L2-resident)
#pragma unroll
        for (int i = 0; i < 8; i++) {
            int d0 = wid * 32 + i * 4;
            float4 v;
            v.x = fmaxf((stg[(d0 + 0) * SPITCH + tok] + z[i].x) * s4[i].x + t4[i].x, 0.0f);
            v.y = fmaxf((stg[(d0 + 1) * SPITCH + tok] + z[i].y) * s4[i].y + t4[i].y, 0.0f);
            v.z = fmaxf((stg[(d0 + 2) * SPITCH + tok] + z[i].z) * s4[i].z + t4[i].z, 0.0f);
            v.w = fmaxf((stg[(d0 + 3) * SPITCH + tok] + z[i].w) * s4[i].w + t4[i].w, 0.0f);
            *(float4*)(ob + (size_t)tok * D_ + d0) = v;
        }
    }
}

extern "C" void kernel_launch(void* const* d_in, const int* in_sizes, int n_in,
                              void* d_out, int out_size) {
    const float* pre_x  = (const float*)d_in[0];
    const float* cur_x  = (const float*)d_in[1];
    const void*  up_idx = d_in[2];
    const float* w      = (const float*)d_in[3];
    const float* bias   = (const float*)d_in[4];
    const float* gamma  = (const float*)d_in[5];
    const float* beta   = (const float*)d_in[6];
    const float* rmean  = (const float*)d_in[7];
    const float* rvar   = (const float*)d_in[8];
    float* out = (float*)d_out;

    cudaFuncSetAttribute(zgemm, cudaFuncAttributeMaxDynamicSharedMemorySize, SMEM_TOTAL);
    cudaFuncSetAttribute(fuse, cudaFuncAttributeMaxDynamicSharedMemorySize, SMEM_TOTAL);

    zgemm<<<dim3(N_ / 64, B_), 128, SMEM_TOTAL>>>(cur_x, w, up_idx);
    fuse<<<dim3(M_ / 64, B_), 128, SMEM_TOTAL>>>(pre_x, w, up_idx, bias, gamma, beta,
                                                 rmean, rvar, out);
}

// round 6
// speedup vs baseline: 1.9789x; 1.9789x over previous
#include <cuda_runtime.h>
#include <cuda_fp16.h>
#include <cstdint>

#define B_   4
#define M_   65536
#define N_   16384
#define D_   128

#define OFF_IDX 0                 // 64 ints (fuse)
#define OFF_SA  1024              // w tile  [64k][136 halfs] = 17408 B
#define OFF_SB  (1024 + 17408)    // x tile  [64k][136 halfs] = 17408 B
#define SMEM_TOTAL (1024 + 2 * 17408)   // 35840
#define OFF_STG 1024              // stage [64tok][132 words] fp32 = 33792 B (aliases SA+SB)
#define TPITCH  132               // words; 2*132 % 32 = 8 -> conflict-free frag scatter
#define PITCHB  272               // 136 halfs * 2 bytes

__device__ float g_Z[(size_t)B_ * N_ * D_];   // 32 MB scratch [b][n][d]
__device__ int g_idx_is64;

// ---------------- helpers ----------------
static __device__ __forceinline__ uint32_t s2u(const void* p) {
    uint32_t a;
    asm("{ .reg .u64 t; cvta.to.shared.u64 t, %1; cvt.u32.u64 %0, t; }" : "=r"(a) : "l"(p));
    return a;
}
static __device__ __forceinline__ uint32_t pk(float lo, float hi) {
    uint32_t r;
    asm("cvt.rn.f16x2.f32 %0, %1, %2;" : "=r"(r) : "f"(hi), "f"(lo));
    return r;
}
static __device__ __forceinline__ void mma_f16(float* c, const uint32_t* a,
                                               uint32_t b0, uint32_t b1) {
    asm volatile(
        "mma.sync.aligned.m16n8k16.row.col.f32.f16.f16.f32 "
        "{%0,%1,%2,%3}, {%4,%5,%6,%7}, {%8,%9}, {%0,%1,%2,%3};"
        : "+f"(c[0]), "+f"(c[1]), "+f"(c[2]), "+f"(c[3])
        : "r"(a[0]), "r"(a[1]), "r"(a[2]), "r"(a[3]), "r"(b0), "r"(b1));
}
#define LDSM4T(r0, r1, r2, r3, a) \
    asm volatile("ldmatrix.sync.aligned.m8n8.x4.trans.shared.b16 {%0,%1,%2,%3}, [%4];" \
                 : "=r"(r0), "=r"(r1), "=r"(r2), "=r"(r3) : "r"(a))
#define LDSM2T(r0, r1, a) \
    asm volatile("ldmatrix.sync.aligned.m8n8.x2.trans.shared.b16 {%0,%1}, [%2];" \
                 : "=r"(r0), "=r"(r1) : "r"(a))

// convert 64 rows x (C4*4) fp32 cols -> f16 smem tile [k][col], pitch 272B
template <int C4>
static __device__ __forceinline__ void conv_tile(char* smc, int offs,
                                                 const float* __restrict__ src,
                                                 size_t stride, int t) {
#pragma unroll
    for (int idx = t, it = 0; it < 64 * C4 / 128; it++, idx += 128) {
        int k = idx / C4, c = idx % C4;
        float4 v = *(const float4*)(src + (size_t)k * stride + c * 4);
        uint2 u = make_uint2(pk(v.x, v.y), pk(v.z, v.w));
        *(uint2*)(smc + offs + k * PITCHB + c * 8) = u;
    }
}

// mainloop over one K=64 chunk: warp tile 64d x 32tok, 64 MMAs
static __device__ __forceinline__ void compute_chunk(uint32_t sb, int wm, int wn, int lane,
                                                     float acc[4][4][4]) {
    const int aRow = (lane & 7) | ((lane & 16) >> 1);
    const int aCol = (lane & 8);
    const int bRow = lane & 15;
#pragma unroll
    for (int ks = 0; ks < 4; ks++) {
        uint32_t A[4][4];
#pragma unroll
        for (int mt = 0; mt < 4; mt++)
            LDSM4T(A[mt][0], A[mt][1], A[mt][2], A[mt][3],
                   sb + OFF_SA + (ks * 16 + aRow) * PITCHB +
                       (wm * 64 + mt * 16 + aCol) * 2);
        uint32_t Bf[4][2];
#pragma unroll
        for (int nt = 0; nt < 4; nt++)
            LDSM2T(Bf[nt][0], Bf[nt][1],
                   sb + OFF_SB + (ks * 16 + bRow) * PITCHB + (wn * 32 + nt * 8) * 2);
#pragma unroll
        for (int mt = 0; mt < 4; mt++)
#pragma unroll
            for (int nt = 0; nt < 4; nt++)
                mma_f16(acc[mt][nt], A[mt], Bf[nt][0], Bf[nt][1]);
    }
}

// scatter accumulators to smem stage [tok][d], pitch TPITCH (conflict-free)
static __device__ __forceinline__ void stage_acc(char* smc, int wm, int wn, int lane,
                                                 float acc[4][4][4]) {
    float* stg = (float*)(smc + OFF_STG);
    const int r = lane >> 2, q2 = (lane & 3) * 2;
#pragma unroll
    for (int mt = 0; mt < 4; mt++)
#pragma unroll
        for (int nt = 0; nt < 4; nt++) {
            int d = wm * 64 + mt * 16 + r;
            int tk = wn * 32 + nt * 8 + q2;
            stg[tk * TPITCH + d]           = acc[mt][nt][0];
            stg[(tk + 1) * TPITCH + d]     = acc[mt][nt][1];
            stg[tk * TPITCH + d + 8]       = acc[mt][nt][2];
            stg[(tk + 1) * TPITCH + d + 8] = acc[mt][nt][3];
        }
}

// ---------------- GEMM 1: Z[b][n][d] = cur_x[b,:,n] @ w[64: ,:] ----------------
__global__ void __launch_bounds__(128, 4) zgemm(const float* __restrict__ cur,
                                                const float* __restrict__ w,
                                                const void* __restrict__ up_idx) {
    extern __shared__ char smc[];
    uint32_t sb = s2u(smc);
    const int t = threadIdx.x, lane = t & 31, wid = t >> 5;
    const int wm = wid & 1, wn = wid >> 1;
    const int bb = blockIdx.y, tok0 = blockIdx.x * 64;

    if (blockIdx.x == 0 && blockIdx.y == 0 && t == 0) {
        const long long* p = (const long long*)up_idx;
        int ok = 1;
        for (int i = 0; i < 64; i++) {
            long long v = p[i];
            if (v < 0 || v >= N_) { ok = 0; break; }
        }
        g_idx_is64 = ok;
    }

    float acc[4][4][4];
#pragma unroll
    for (int a = 0; a < 4; a++)
#pragma unroll
        for (int b = 0; b < 4; b++)
#pragma unroll
            for (int c = 0; c < 4; c++) acc[a][b][c] = 0.0f;

    const float* xb = cur + (size_t)bb * 128 * N_ + tok0;
#pragma unroll
    for (int c = 0; c < 2; c++) {
        conv_tile<32>(smc, OFF_SA, w + (size_t)(64 + c * 64) * D_, D_, t);
        conv_tile<16>(smc, OFF_SB, xb + (size_t)c * 64 * N_, N_, t);
        __syncthreads();
        compute_chunk(sb, wm, wn, lane, acc);
        __syncthreads();
    }
    stage_acc(smc, wm, wn, lane, acc);
    __syncthreads();

    // coalesced Z store: warp owns 16 tokens, lanes span d
    const float* stg = (const float*)(smc + OFF_STG);
    float* zb = g_Z + ((size_t)bb * N_ + tok0) * D_ + lane * 4;
#pragma unroll
    for (int i = 0; i < 16; i++) {
        int tok = wid * 16 + i;
        float4 v = *(const float4*)(stg + tok * TPITCH + lane * 4);
        *(float4*)(zb + (size_t)tok * D_) = v;
    }
}

// ---------------- GEMM 2 + gather + BN + relu ----------------
__global__ void __launch_bounds__(128, 4) fuse(const float* __restrict__ pre,
                                               const float* __restrict__ w,
                                               const void* __restrict__ up_idx,
                                               const float* __restrict__ bias,
                                               const float* __restrict__ gamma,
                                               const float* __restrict__ beta,
                                               const float* __restrict__ rmean,
                                               const float* __restrict__ rvar,
                                               float* __restrict__ out) {
    extern __shared__ char smc[];
    uint32_t sb = s2u(smc);
    const int t = threadIdx.x, lane = t & 31, wid = t >> 5;
    const int wm = wid & 1, wn = wid >> 1;
    const int bb = blockIdx.y, tok0 = blockIdx.x * 64;

    int* sIdx = (int*)(smc + OFF_IDX);
    if (t < 64) {
        size_t ip = (size_t)bb * M_ + tok0 + t;
        sIdx[t] = g_idx_is64 ? (int)((const long long*)up_idx)[ip]
                             : ((const int*)up_idx)[ip];
    }

    float acc[4][4][4];
#pragma unroll
    for (int a = 0; a < 4; a++)
#pragma unroll
        for (int b = 0; b < 4; b++)
#pragma unroll
            for (int c = 0; c < 4; c++) acc[a][b][c] = 0.0f;

    conv_tile<32>(smc, OFF_SA, w, D_, t);
    conv_tile<16>(smc, OFF_SB, pre + (size_t)bb * 64 * M_ + tok0, M_, t);
    __syncthreads();
    compute_chunk(sb, wm, wn, lane, acc);
    __syncthreads();
    stage_acc(smc, wm, wn, lane, acc);

    // per-lane BN fold for d = lane*4 .. lane*4+3 (2 float4 regs)
    float4 s4, t4;
    {
        int d0 = lane * 4;
        float4 rv = *(const float4*)(rvar + d0);
        float4 gm = *(const float4*)(gamma + d0);
        float4 bi = *(const float4*)(bias + d0);
        float4 rm = *(const float4*)(rmean + d0);
        float4 be = *(const float4*)(beta + d0);
        s4.x = rsqrtf(rv.x + 1e-5f) * gm.x;
        s4.y = rsqrtf(rv.y + 1e-5f) * gm.y;
        s4.z = rsqrtf(rv.z + 1e-5f) * gm.z;
        s4.w = rsqrtf(rv.w + 1e-5f) * gm.w;
        t4.x = (bi.x - rm.x) * s4.x + be.x;
        t4.y = (bi.y - rm.y) * s4.y + be.y;
        t4.z = (bi.z - rm.z) * s4.z + be.z;
        t4.w = (bi.w - rm.w) * s4.w + be.w;
    }
    __syncthreads();

    // coalesced epilogue: warp owns 16 tokens; per token 512B gather + 512B store
    const float* stg = (const float*)(smc + OFF_STG);
    const float* zB = g_Z + (size_t)bb * N_ * D_ + lane * 4;
    float* ob = out + ((size_t)bb * M_ + tok0) * D_ + lane * 4;

    float4 z[16];
#pragma unroll
    for (int i = 0; i < 16; i++)                  // batch gathers for MLP
        z[i] = *(const float4*)(zB + (size_t)sIdx[wid * 16 + i] * D_);
#pragma unroll
    for (int i = 0; i < 16; i++) {
        int tok = wid * 16 + i;
        float4 a = *(const float4*)(stg + tok * TPITCH + lane * 4);
        float4 v;
        v.x = fmaxf((a.x + z[i].x) * s4.x + t4.x, 0.0f);
        v.y = fmaxf((a.y + z[i].y) * s4.y + t4.y, 0.0f);
        v.z = fmaxf((a.z + z[i].z) * s4.z + t4.z, 0.0f);
        v.w = fmaxf((a.w + z[i].w) * s4.w + t4.w, 0.0f);
        *(float4*)(ob + (size_t)tok * D_) = v;
    }
}

extern "C" void kernel_launch(void* const* d_in, const int* in_sizes, int n_in,
                              void* d_out, int out_size) {
    const float* pre_x  = (const float*)d_in[0];
    const float* cur_x  = (const float*)d_in[1];
    const void*  up_idx = d_in[2];
    const float* w      = (const float*)d_in[3];
    const float* bias   = (const float*)d_in[4];
    const float* gamma  = (const float*)d_in[5];
    const float* beta   = (const float*)d_in[6];
    const float* rmean  = (const float*)d_in[7];
    const float* rvar   = (const float*)d_in[8];
    float* out = (float*)d_out;

    cudaFuncSetAttribute(zgemm, cudaFuncAttributeMaxDynamicSharedMemorySize, SMEM_TOTAL);
    cudaFuncSetAttribute(fuse, cudaFuncAttributeMaxDynamicSharedMemorySize, SMEM_TOTAL);

    zgemm<<<dim3(N_ / 64, B_), 128, SMEM_TOTAL>>>(cur_x, w, up_idx);
    fuse<<<dim3(M_ / 64, B_), 128, SMEM_TOTAL>>>(pre_x, w, up_idx, bias, gamma, beta,
                                                 rmean, rvar, out);
}